// round 10
// baseline (speedup 1.0000x reference)
#include <cuda_runtime.h>
#include <cuda_fp16.h>
#include <cstdint>
#include <cstddef>
#include <math.h>

#define BB    256
#define HH    128
#define NNODE 1000
#define NPAD  1024
#define K3    384
#define KC    32          // k per chunk (2 x k16 steps)
#define NCH   (K3 / KC)   // 12
#define NT    64          // n per CTA
#define APAD  40          // As row stride (fp16)
#define BFW   68          // Bf fp32 staging row stride (floats; 68%32=4 -> conflict-free)

#define AS1   (HH * APAD)     // 5120 halfs per A buffer
#define BF1   (KC * BFW)      // 2176 floats per Bf buffer

// ---------------- scratch (__device__ globals) -----------------------------
__device__ float g_dvec[BB * HH];
__device__ float g_attn[BB * NPAD];
__device__ __half g_whi[HH * K3];

// ---------------- helpers --------------------------------------------------
__device__ __forceinline__ uint32_t smem_u32(const void* p) {
    uint32_t a;
    asm("{ .reg .u64 t; cvta.to.shared.u64 t, %1; cvt.u32.u64 %0, t; }" : "=r"(a) : "l"(p));
    return a;
}
#define CP16(dst, src) \
    asm volatile("cp.async.cg.shared.global [%0], [%1], 16;" :: "r"(dst), "l"(src))
#define CP16Z(dst, src, nb) \
    asm volatile("cp.async.cg.shared.global [%0], [%1], 16, %2;" :: "r"(dst), "l"(src), "r"(nb))
#define CP_COMMIT() asm volatile("cp.async.commit_group;")
#define CP_WAIT(n)  asm volatile("cp.async.wait_group %0;" :: "n"(n))

__device__ __forceinline__ void ldsm_x4(uint32_t& r0, uint32_t& r1,
                                        uint32_t& r2, uint32_t& r3, uint32_t a) {
    asm volatile("ldmatrix.sync.aligned.m8n8.x4.shared.b16 {%0,%1,%2,%3}, [%4];"
                 : "=r"(r0), "=r"(r1), "=r"(r2), "=r"(r3) : "r"(a));
}
__device__ __forceinline__ void mma16816(float* c, const uint32_t* a,
                                         uint32_t b0, uint32_t b1) {
    asm volatile("mma.sync.aligned.m16n8k16.row.col.f32.f16.f16.f32 "
                 "{%0,%1,%2,%3}, {%4,%5,%6,%7}, {%8,%9}, {%0,%1,%2,%3};"
                 : "+f"(c[0]), "+f"(c[1]), "+f"(c[2]), "+f"(c[3])
                 : "r"(a[0]), "r"(a[1]), "r"(a[2]), "r"(a[3]), "r"(b0), "r"(b1));
}
// fp32x4 -> packed fp16x4
__device__ __forceinline__ unsigned long long cvt4h(float4 f) {
    __half2 p0 = __floats2half2_rn(f.x, f.y);
    __half2 p1 = __floats2half2_rn(f.z, f.w);
    union { __half2 h[2]; unsigned long long u; } r;
    r.h[0] = p0; r.h[1] = p1;
    return r.u;
}
__device__ __forceinline__ uint32_t pack2h(float a, float b) {
    __half2 p = __floats2half2_rn(a, b);
    return *(uint32_t*)&p;
}
__device__ __forceinline__ float tanh_fast(float x) {
    float t = __expf(2.f * x);
    return 1.f - __fdividef(2.f, t + 1.f);
}

// SMEM layout (bytes)
#define SO_AHI  0                              // 2 x AS1 fp16 = 20480
#define SO_BF   (SO_AHI + 2 * AS1 * 2)         // 20480: 2 x BF1 fp32 = 17408
#define SO_RED  (SO_BF + 2 * BF1 * 4)          // 37888: 4*64 fp32
#define SMEM_SZ (SO_RED + 4 * NT * 4)          // 38912

// ---------------------------------------------------------------------------
// Kernel W-pack: W[:, :384] -> fp16
// ---------------------------------------------------------------------------
__global__ void __launch_bounds__(96) wpack_kernel(const float* __restrict__ W)
{
    int h = blockIdx.x, k = threadIdx.x * 4;
    float4 f = *(const float4*)&W[h * (4 * HH) + k];
    *(unsigned long long*)&g_whi[h * K3 + k] = cvt4h(f);
}

// ---------------------------------------------------------------------------
// Kernel A: d[b,h] = W[h,384:512] . dec[b,:]  (fp32, exact)
// ---------------------------------------------------------------------------
__global__ void __launch_bounds__(HH) dvec_kernel(const float* __restrict__ dec,
                                                  const float* __restrict__ W)
{
    __shared__ float4 sdec[HH / 4];
    int b = blockIdx.x, h = threadIdx.x;
    if (h < HH / 4) sdec[h] = *(const float4*)&dec[b * HH + h * 4];
    __syncthreads();
    const float4* w4 = (const float4*)(W + h * (4 * HH) + 3 * HH);
    float s0 = 0.f, s1 = 0.f, s2 = 0.f, s3 = 0.f;
#pragma unroll 8
    for (int i = 0; i < 32; i++) {
        float4 wv = w4[i];
        float4 dv = sdec[i];
        s0 += wv.x * dv.x; s1 += wv.y * dv.y;
        s2 += wv.z * dv.z; s3 += wv.w * dv.w;
    }
    g_dvec[b * HH + h] = (s0 + s1) + (s2 + s3);
}

// ---------------------------------------------------------------------------
// Kernel B: pipelined fp16 HMMA; B fragments loaded fp32->reg-converted
// ---------------------------------------------------------------------------
__global__ void __launch_bounds__(256, 2)
score_kernel(const float* __restrict__ adj,
             const float* __restrict__ sta,
             const float* __restrict__ dyn,
             const float* __restrict__ v)
{
    extern __shared__ __align__(16) char smem[];
    __half* As_hi = (__half*)(smem + SO_AHI);
    float*  Bf    = (float*)(smem + SO_BF);
    float*  red   = (float*)(smem + SO_RED);

    const int tid  = threadIdx.x;
    const int lane = tid & 31;
    const int wrp  = tid >> 5;
    const int wm   = wrp >> 1;       // 0..3 (h quarter)
    const int wn   = wrp & 1;        // 0..1 (n half)
    const int b  = blockIdx.y;
    const int n0 = blockIdx.x * NT;

    const float* srcs[3] = {
        adj + (size_t)b * HH * NNODE,
        sta + (size_t)b * HH * NNODE,
        dyn + (size_t)b * HH * NNODE };

    const uint32_t uAhi = smem_u32(As_hi);
    const uint32_t uBf  = smem_u32(Bf);
    auto stage = [&](int it, int s) {
        const int k0 = it * KC;
        // A: g_whi[h][k0..k0+31], 16B chunks (8 fp16)
#pragma unroll
        for (int i = 0; i < 2; i++) {
            int idx = tid + i * 256;
            int row = idx >> 2, q = idx & 3;
            uint32_t doff = (uint32_t)((s * AS1 + row * APAD + q * 8) * 2);
            CP16(uAhi + doff, &g_whi[row * K3 + k0 + q * 8]);
        }
        // B: hidden[b][k0+k][n0..n0+63] fp32, zero-fill OOB
#pragma unroll
        for (int i = 0; i < 2; i++) {
            int idx = tid + i * 256;
            int krow = idx >> 4, q = idx & 15;
            int kg = k0 + krow;
            const float* src = srcs[kg >> 7] + (size_t)(kg & 127) * NNODE + n0 + q * 4;
            uint32_t doff = (uint32_t)((s * BF1 + krow * BFW + q * 4) * 4);
            uint32_t nb = (n0 + q * 4 < NNODE) ? 16u : 0u;
            CP16Z(uBf + doff, src, nb);
        }
        CP_COMMIT();
    };

    float acc[2][4][4];
#pragma unroll
    for (int mt = 0; mt < 2; mt++)
#pragma unroll
        for (int nt = 0; nt < 4; nt++)
#pragma unroll
            for (int c = 0; c < 4; c++) acc[mt][nt][c] = 0.f;

    const int aRow = wm * 32 + (lane & 15);        // + mt*16
    const int aCol = (lane >> 4) * 8;              // + ks*16
    // B direct-fragment indices: c = lane%4 (k pair), nn = lane/4 (n within group)
    const int fc = lane & 3;
    const int fn = wn * 32 + (lane >> 2);          // + nt*8

    stage(0, 0);                                    // prologue

    for (int it = 0; it < NCH; it++) {
        const int s = it & 1;
        // BARRIER 1: prev compute reads of As[s^1]/Bf[s^1] done before overwrite
        __syncthreads();
        if (it + 1 < NCH) { stage(it + 1, s ^ 1); CP_WAIT(1); }
        else              { CP_WAIT(0); }
        // BARRIER 2: stage s data visible
        __syncthreads();

        const uint32_t aOffS = (uint32_t)(s * AS1 * 2);
        const float* bfS = Bf + s * BF1;
#pragma unroll
        for (int ks = 0; ks < 2; ks++) {
            uint32_t ah[2][4];
#pragma unroll
            for (int mt = 0; mt < 2; mt++) {
                uint32_t off = aOffS + (uint32_t)(((aRow + mt * 16) * APAD + ks * 16 + aCol) * 2);
                ldsm_x4(ah[mt][0], ah[mt][1], ah[mt][2], ah[mt][3], uAhi + off);
            }
            // direct B fragment loads (fp32 smem -> fp16 regs)
            const int kb = ks * 16 + fc * 2;
            uint32_t b0[4], b1[4];
#pragma unroll
            for (int nt = 0; nt < 4; nt++) {
                const float* p = bfS + fn + nt * 8;
                float x0 = p[(kb + 0) * BFW], x1 = p[(kb + 1) * BFW];
                float x8 = p[(kb + 8) * BFW], x9 = p[(kb + 9) * BFW];
                b0[nt] = pack2h(x0, x1);
                b1[nt] = pack2h(x8, x9);
            }
#pragma unroll
            for (int mt = 0; mt < 2; mt++)
#pragma unroll
                for (int nt = 0; nt < 4; nt++)
                    mma16816(acc[mt][nt], ah[mt], b0[nt], b1[nt]);
        }
    }

    // ---- epilogue: tanh(acc + d) * v, reduce over h
    const int g = lane >> 2, t = lane & 3;
    const float* dp = g_dvec + b * HH;
    float d0[2], d1[2], v0[2], v1[2];
#pragma unroll
    for (int mt = 0; mt < 2; mt++) {
        int h0 = wm * 32 + mt * 16 + g;
        d0[mt] = dp[h0];     d1[mt] = dp[h0 + 8];
        v0[mt] = v[h0];      v1[mt] = v[h0 + 8];
    }
    float p[4][2];
#pragma unroll
    for (int nt = 0; nt < 4; nt++)
#pragma unroll
        for (int c = 0; c < 2; c++) {
            float sacc = 0.f;
#pragma unroll
            for (int mt = 0; mt < 2; mt++)
                sacc += v0[mt] * tanh_fast(acc[mt][nt][c]     + d0[mt])
                      + v1[mt] * tanh_fast(acc[mt][nt][c + 2] + d1[mt]);
            p[nt][c] = sacc;
        }
#pragma unroll
    for (int m = 4; m <= 16; m <<= 1)
#pragma unroll
        for (int nt = 0; nt < 4; nt++)
#pragma unroll
            for (int c = 0; c < 2; c++)
                p[nt][c] += __shfl_xor_sync(0xFFFFFFFFu, p[nt][c], m);
    if (g == 0) {
#pragma unroll
        for (int nt = 0; nt < 4; nt++)
#pragma unroll
            for (int c = 0; c < 2; c++)
                red[wm * NT + wn * 32 + nt * 8 + t * 2 + c] = p[nt][c];
    }
    __syncthreads();
    if (tid < NT) {
        float sacc = red[0*NT+tid] + red[1*NT+tid] + red[2*NT+tid] + red[3*NT+tid];
        int n = n0 + tid;
        if (n < NNODE) g_attn[b * NPAD + n] = sacc;
    }
}

// ---------------------------------------------------------------------------
// Kernel C: row softmax
// ---------------------------------------------------------------------------
__global__ void __launch_bounds__(256) softmax_kernel(float* __restrict__ out)
{
    __shared__ float sred[256];
    const int b = blockIdx.x, tid = threadIdx.x;
    const float* row = &g_attn[b * NPAD];

    float m = -INFINITY;
    for (int n = tid; n < NNODE; n += 256) m = fmaxf(m, row[n]);
    sred[tid] = m;  __syncthreads();
    for (int s = 128; s > 0; s >>= 1) {
        if (tid < s) sred[tid] = fmaxf(sred[tid], sred[tid + s]);
        __syncthreads();
    }
    m = sred[0];  __syncthreads();

    float sum = 0.f;
    for (int n = tid; n < NNODE; n += 256) sum += __expf(row[n] - m);
    sred[tid] = sum;  __syncthreads();
    for (int s = 128; s > 0; s >>= 1) {
        if (tid < s) sred[tid] += sred[tid + s];
        __syncthreads();
    }
    float inv = 1.f / sred[0];

    for (int n = tid; n < NNODE; n += 256)
        out[b * NNODE + n] = __expf(row[n] - m) * inv;
}

// ---------------------------------------------------------------------------
extern "C" void kernel_launch(void* const* d_in, const int* in_sizes, int n_in,
                              void* d_out, int out_size)
{
    const float* adj = (const float*)d_in[0];
    const float* sta = (const float*)d_in[1];
    const float* dyn = (const float*)d_in[2];
    const float* dec = (const float*)d_in[3];
    const float* v   = (const float*)d_in[4];
    const float* W   = (const float*)d_in[5];
    float* out = (float*)d_out;

    cudaFuncSetAttribute(score_kernel,
                         cudaFuncAttributeMaxDynamicSharedMemorySize, SMEM_SZ);

    wpack_kernel<<<HH, 96>>>(W);
    dvec_kernel<<<BB, HH>>>(dec, W);
    dim3 grid(NPAD / NT, BB);                    // (16, 256)
    score_kernel<<<grid, 256, SMEM_SZ>>>(adj, sta, dyn, v);
    softmax_kernel<<<BB, 256>>>(out);
}

// round 11
// speedup vs baseline: 1.0648x; 1.0648x over previous
#include <cuda_runtime.h>
#include <cuda_fp16.h>
#include <cstdint>
#include <cstddef>
#include <math.h>

#define BB    256
#define HH    128
#define NNODE 1000
#define NPAD  1024
#define K3    384
#define KC    32          // k per chunk (2 x k16 steps)
#define NCH   (K3 / KC)   // 12
#define NT    64          // n per CTA
#define NTILES (NPAD / NT) // 16 CTAs per batch
#define APAD  40          // As row stride (fp16)
#define BPAD  72          // Bs row stride (fp16)
#define BFW   64          // Bf fp32 staging row stride (floats)

#define AS1   (HH * APAD)     // 5120 halfs per A buffer
#define BF1   (KC * BFW)      // 2048 floats per Bf buffer

// ---------------- scratch (__device__ globals) -----------------------------
__device__ float g_dvec[BB * HH];
__device__ float g_attn[BB * NPAD];
__device__ __half g_whi[HH * K3];
__device__ int   g_cnt[BB];              // zero-initialized; reset after use

// ---------------- helpers --------------------------------------------------
__device__ __forceinline__ uint32_t smem_u32(const void* p) {
    uint32_t a;
    asm("{ .reg .u64 t; cvta.to.shared.u64 t, %1; cvt.u32.u64 %0, t; }" : "=r"(a) : "l"(p));
    return a;
}
#define CP16(dst, src) \
    asm volatile("cp.async.cg.shared.global [%0], [%1], 16;" :: "r"(dst), "l"(src))
#define CP16Z(dst, src, nb) \
    asm volatile("cp.async.cg.shared.global [%0], [%1], 16, %2;" :: "r"(dst), "l"(src), "r"(nb))
#define CP_COMMIT() asm volatile("cp.async.commit_group;")
#define CP_WAIT(n)  asm volatile("cp.async.wait_group %0;" :: "n"(n))

__device__ __forceinline__ void ldsm_x4(uint32_t& r0, uint32_t& r1,
                                        uint32_t& r2, uint32_t& r3, uint32_t a) {
    asm volatile("ldmatrix.sync.aligned.m8n8.x4.shared.b16 {%0,%1,%2,%3}, [%4];"
                 : "=r"(r0), "=r"(r1), "=r"(r2), "=r"(r3) : "r"(a));
}
__device__ __forceinline__ void ldsm_x4_t(uint32_t& r0, uint32_t& r1,
                                          uint32_t& r2, uint32_t& r3, uint32_t a) {
    asm volatile("ldmatrix.sync.aligned.m8n8.x4.trans.shared.b16 {%0,%1,%2,%3}, [%4];"
                 : "=r"(r0), "=r"(r1), "=r"(r2), "=r"(r3) : "r"(a));
}
__device__ __forceinline__ void mma16816(float* c, const uint32_t* a,
                                         uint32_t b0, uint32_t b1) {
    asm volatile("mma.sync.aligned.m16n8k16.row.col.f32.f16.f16.f32 "
                 "{%0,%1,%2,%3}, {%4,%5,%6,%7}, {%8,%9}, {%0,%1,%2,%3};"
                 : "+f"(c[0]), "+f"(c[1]), "+f"(c[2]), "+f"(c[3])
                 : "r"(a[0]), "r"(a[1]), "r"(a[2]), "r"(a[3]), "r"(b0), "r"(b1));
}
// fp32x4 -> packed fp16x4
__device__ __forceinline__ unsigned long long cvt4h(float4 f) {
    __half2 p0 = __floats2half2_rn(f.x, f.y);
    __half2 p1 = __floats2half2_rn(f.z, f.w);
    union { __half2 h[2]; unsigned long long u; } r;
    r.h[0] = p0; r.h[1] = p1;
    return r.u;
}
__device__ __forceinline__ float tanh_fast(float x) {
    float t = __expf(2.f * x);
    return 1.f - __fdividef(2.f, t + 1.f);
}

// SMEM layout (bytes)
#define SO_AHI  0                              // 2 x AS1 fp16 = 20480
#define SO_BF   (SO_AHI + 2 * AS1 * 2)         // 20480: 2 x BF1 fp32 = 16384
#define SO_BSH  (SO_BF + 2 * BF1 * 4)          // 36864: KC*BPAD fp16 = 4608
#define SO_RED  (SO_BSH + KC * BPAD * 2)       // 41472: 4*64 fp32 = 1024
#define SO_SMX  (SO_RED + 4 * NT * 4)          // 42496: 256 fp32 = 1024
#define SMEM_SZ (SO_SMX + 256 * 4)             // 43520  (x3 CTA = 130.5KB)

// ---------------------------------------------------------------------------
// Kernel W-pack: W[:, :384] -> fp16
// ---------------------------------------------------------------------------
__global__ void __launch_bounds__(96) wpack_kernel(const float* __restrict__ W)
{
    int h = blockIdx.x, k = threadIdx.x * 4;
    float4 f = *(const float4*)&W[h * (4 * HH) + k];
    *(unsigned long long*)&g_whi[h * K3 + k] = cvt4h(f);
}

// ---------------------------------------------------------------------------
// Kernel A: d[b,h] = W[h,384:512] . dec[b,:]  (fp32, exact)
// ---------------------------------------------------------------------------
__global__ void __launch_bounds__(HH) dvec_kernel(const float* __restrict__ dec,
                                                  const float* __restrict__ W)
{
    __shared__ float4 sdec[HH / 4];
    int b = blockIdx.x, h = threadIdx.x;
    if (h < HH / 4) sdec[h] = *(const float4*)&dec[b * HH + h * 4];
    __syncthreads();
    const float4* w4 = (const float4*)(W + h * (4 * HH) + 3 * HH);
    float s0 = 0.f, s1 = 0.f, s2 = 0.f, s3 = 0.f;
#pragma unroll 8
    for (int i = 0; i < 32; i++) {
        float4 wv = w4[i];
        float4 dv = sdec[i];
        s0 += wv.x * dv.x; s1 += wv.y * dv.y;
        s2 += wv.z * dv.z; s3 += wv.w * dv.w;
    }
    g_dvec[b * HH + h] = (s0 + s1) + (s2 + s3);
}

// ---------------------------------------------------------------------------
// Kernel B: pipelined single-product fp16 HMMA GEMM + tanh/v epilogue
//           + fused per-batch softmax (last finishing CTA of each batch)
// ---------------------------------------------------------------------------
__global__ void __launch_bounds__(256, 3)
score_kernel(const float* __restrict__ adj,
             const float* __restrict__ sta,
             const float* __restrict__ dyn,
             const float* __restrict__ v,
             float* __restrict__ out)
{
    extern __shared__ __align__(16) char smem[];
    __half* As_hi = (__half*)(smem + SO_AHI);
    float*  Bf    = (float*)(smem + SO_BF);
    __half* Bs_h  = (__half*)(smem + SO_BSH);
    float*  red   = (float*)(smem + SO_RED);
    float*  smx   = (float*)(smem + SO_SMX);

    const int tid  = threadIdx.x;
    const int lane = tid & 31;
    const int wrp  = tid >> 5;
    const int wm   = wrp >> 1;       // 0..3 (h quarter)
    const int wn   = wrp & 1;        // 0..1 (n half)
    const int b  = blockIdx.y;
    const int n0 = blockIdx.x * NT;

    const float* srcs[3] = {
        adj + (size_t)b * HH * NNODE,
        sta + (size_t)b * HH * NNODE,
        dyn + (size_t)b * HH * NNODE };

    const uint32_t uAhi = smem_u32(As_hi);
    const uint32_t uBf  = smem_u32(Bf);
    auto stage = [&](int it, int s) {
        const int k0 = it * KC;
#pragma unroll
        for (int i = 0; i < 2; i++) {
            int idx = tid + i * 256;
            int row = idx >> 2, q = idx & 3;
            uint32_t doff = (uint32_t)((s * AS1 + row * APAD + q * 8) * 2);
            CP16(uAhi + doff, &g_whi[row * K3 + k0 + q * 8]);
        }
#pragma unroll
        for (int i = 0; i < 2; i++) {
            int idx = tid + i * 256;
            int krow = idx >> 4, q = idx & 15;
            int kg = k0 + krow;
            const float* src = srcs[kg >> 7] + (size_t)(kg & 127) * NNODE + n0 + q * 4;
            uint32_t doff = (uint32_t)((s * BF1 + krow * BFW + q * 4) * 4);
            uint32_t nb = (n0 + q * 4 < NNODE) ? 16u : 0u;
            CP16Z(uBf + doff, src, nb);
        }
        CP_COMMIT();
    };

    float acc[2][4][4];
#pragma unroll
    for (int mt = 0; mt < 2; mt++)
#pragma unroll
        for (int nt = 0; nt < 4; nt++)
#pragma unroll
            for (int c = 0; c < 4; c++) acc[mt][nt][c] = 0.f;

    const uint32_t bshU = smem_u32(Bs_h);
    const int aRow = wm * 32 + (lane & 15);        // + mt*16
    const int aCol = (lane >> 4) * 8;              // + ks*16
    const int bRow = (lane & 15);                  // + ks*16
    const int bCol = wn * 32 + (lane >> 4) * 8;    // + ntg*16

    stage(0, 0);                                    // prologue

    for (int it = 0; it < NCH; it++) {
        const int s = it & 1;
        __syncthreads();                            // prev reads done
        if (it + 1 < NCH) { stage(it + 1, s ^ 1); CP_WAIT(1); }
        else              { CP_WAIT(0); }
        __syncthreads();                            // stage s visible

        // ---- convert B fp32 -> fp16
#pragma unroll
        for (int i = 0; i < 2; i++) {
            int idx = tid + i * 256;
            int krow = idx >> 4, q = idx & 15;
            float4 f = *(float4*)&Bf[s * BF1 + krow * BFW + q * 4];
            *(unsigned long long*)&Bs_h[krow * BPAD + q * 4] = cvt4h(f);
        }
        __syncthreads();                            // Bs ready

        const uint32_t aOffS = (uint32_t)(s * AS1 * 2);
#pragma unroll
        for (int ks = 0; ks < 2; ks++) {
            uint32_t ah[2][4];
#pragma unroll
            for (int mt = 0; mt < 2; mt++) {
                uint32_t off = aOffS + (uint32_t)(((aRow + mt * 16) * APAD + ks * 16 + aCol) * 2);
                ldsm_x4(ah[mt][0], ah[mt][1], ah[mt][2], ah[mt][3], uAhi + off);
            }
            uint32_t bh[8];
#pragma unroll
            for (int ntg = 0; ntg < 2; ntg++) {
                uint32_t off = (uint32_t)(((ks * 16 + bRow) * BPAD + bCol + ntg * 16) * 2);
                ldsm_x4_t(bh[ntg*4+0], bh[ntg*4+1], bh[ntg*4+2], bh[ntg*4+3], bshU + off);
            }
#pragma unroll
            for (int mt = 0; mt < 2; mt++)
#pragma unroll
                for (int nt = 0; nt < 4; nt++)
                    mma16816(acc[mt][nt], ah[mt], bh[nt*2+0], bh[nt*2+1]);
        }
    }

    // ---- epilogue: tanh(acc + d) * v, reduce over h -> logits
    const int g = lane >> 2, t = lane & 3;
    const float* dp = g_dvec + b * HH;
    float d0[2], d1[2], v0[2], v1[2];
#pragma unroll
    for (int mt = 0; mt < 2; mt++) {
        int h0 = wm * 32 + mt * 16 + g;
        d0[mt] = dp[h0];     d1[mt] = dp[h0 + 8];
        v0[mt] = v[h0];      v1[mt] = v[h0 + 8];
    }
    float p[4][2];
#pragma unroll
    for (int nt = 0; nt < 4; nt++)
#pragma unroll
        for (int c = 0; c < 2; c++) {
            float sacc = 0.f;
#pragma unroll
            for (int mt = 0; mt < 2; mt++)
                sacc += v0[mt] * tanh_fast(acc[mt][nt][c]     + d0[mt])
                      + v1[mt] * tanh_fast(acc[mt][nt][c + 2] + d1[mt]);
            p[nt][c] = sacc;
        }
#pragma unroll
    for (int m = 4; m <= 16; m <<= 1)
#pragma unroll
        for (int nt = 0; nt < 4; nt++)
#pragma unroll
            for (int c = 0; c < 2; c++)
                p[nt][c] += __shfl_xor_sync(0xFFFFFFFFu, p[nt][c], m);
    if (g == 0) {
#pragma unroll
        for (int nt = 0; nt < 4; nt++)
#pragma unroll
            for (int c = 0; c < 2; c++)
                red[wm * NT + wn * 32 + nt * 8 + t * 2 + c] = p[nt][c];
    }
    __syncthreads();
    if (tid < NT) {
        float sacc = red[0*NT+tid] + red[1*NT+tid] + red[2*NT+tid] + red[3*NT+tid];
        int n = n0 + tid;
        if (n < NNODE) g_attn[b * NPAD + n] = sacc;
    }

    // ---- fused softmax: last CTA of batch b does the row softmax
    __shared__ int is_last;
    __syncthreads();              // all logit writes issued
    __threadfence();              // order this CTA's writes before the count
    if (tid == 0) is_last = (atomicAdd(&g_cnt[b], 1) == NTILES - 1);
    __syncthreads();
    if (is_last) {
        const float* row = &g_attn[b * NPAD];
        float m = -INFINITY;
        for (int n = tid; n < NNODE; n += 256) m = fmaxf(m, row[n]);
        smx[tid] = m;  __syncthreads();
        for (int sred = 128; sred > 0; sred >>= 1) {
            if (tid < sred) smx[tid] = fmaxf(smx[tid], smx[tid + sred]);
            __syncthreads();
        }
        m = smx[0];  __syncthreads();

        float sum = 0.f;
        for (int n = tid; n < NNODE; n += 256) sum += __expf(row[n] - m);
        smx[tid] = sum;  __syncthreads();
        for (int sred = 128; sred > 0; sred >>= 1) {
            if (tid < sred) smx[tid] += smx[tid + sred];
            __syncthreads();
        }
        float inv = 1.f / smx[0];

        for (int n = tid; n < NNODE; n += 256)
            out[b * NNODE + n] = __expf(row[n] - m) * inv;

        __syncthreads();
        if (tid == 0) g_cnt[b] = 0;   // reset for next graph replay
    }
}

// ---------------------------------------------------------------------------
extern "C" void kernel_launch(void* const* d_in, const int* in_sizes, int n_in,
                              void* d_out, int out_size)
{
    const float* adj = (const float*)d_in[0];
    const float* sta = (const float*)d_in[1];
    const float* dyn = (const float*)d_in[2];
    const float* dec = (const float*)d_in[3];
    const float* v   = (const float*)d_in[4];
    const float* W   = (const float*)d_in[5];
    float* out = (float*)d_out;

    cudaFuncSetAttribute(score_kernel,
                         cudaFuncAttributeMaxDynamicSharedMemorySize, SMEM_SZ);

    wpack_kernel<<<HH, 96>>>(W);
    dvec_kernel<<<BB, HH>>>(dec, W);
    dim3 grid(NTILES, BB);                       // (16, 256)
    score_kernel<<<grid, 256, SMEM_SZ>>>(adj, sta, dyn, v, out);
}

// round 12
// speedup vs baseline: 1.1288x; 1.0601x over previous
#include <cuda_runtime.h>
#include <cuda_fp16.h>
#include <cstdint>
#include <cstddef>
#include <math.h>

#define BB    256
#define HH    128
#define NNODE 1000
#define NPAD  1024
#define K3    384
#define KC    64          // k per chunk (4 x k16 steps)
#define NCH   (K3 / KC)   // 6
#define NT    64          // n per CTA
#define NTILES (NPAD / NT) // 16 CTAs per batch
#define APAD  72          // As row stride (fp16): 64 k + 8 pad, conflict-free
#define BPAD  72          // Bs row stride (fp16)
#define BFW   68          // Bf fp32 staging row stride (floats)

#define AS1   (HH * APAD)     // 9216 halfs per A buffer
#define BF1   (KC * BFW)      // 4352 floats per Bf buffer

// ---------------- scratch (__device__ globals) -----------------------------
__device__ float g_dvec[BB * HH];
__device__ float g_attn[BB * NPAD];
__device__ __half g_whi[HH * K3];
__device__ int   g_cnt[BB];              // zero-init; reset after use (graph-safe)

// ---------------- helpers --------------------------------------------------
__device__ __forceinline__ uint32_t smem_u32(const void* p) {
    uint32_t a;
    asm("{ .reg .u64 t; cvta.to.shared.u64 t, %1; cvt.u32.u64 %0, t; }" : "=r"(a) : "l"(p));
    return a;
}
#define CP16(dst, src) \
    asm volatile("cp.async.cg.shared.global [%0], [%1], 16;" :: "r"(dst), "l"(src))
#define CP16Z(dst, src, nb) \
    asm volatile("cp.async.cg.shared.global [%0], [%1], 16, %2;" :: "r"(dst), "l"(src), "r"(nb))
#define CP_COMMIT() asm volatile("cp.async.commit_group;")
#define CP_WAIT(n)  asm volatile("cp.async.wait_group %0;" :: "n"(n))

__device__ __forceinline__ void ldsm_x4(uint32_t& r0, uint32_t& r1,
                                        uint32_t& r2, uint32_t& r3, uint32_t a) {
    asm volatile("ldmatrix.sync.aligned.m8n8.x4.shared.b16 {%0,%1,%2,%3}, [%4];"
                 : "=r"(r0), "=r"(r1), "=r"(r2), "=r"(r3) : "r"(a));
}
__device__ __forceinline__ void ldsm_x4_t(uint32_t& r0, uint32_t& r1,
                                          uint32_t& r2, uint32_t& r3, uint32_t a) {
    asm volatile("ldmatrix.sync.aligned.m8n8.x4.trans.shared.b16 {%0,%1,%2,%3}, [%4];"
                 : "=r"(r0), "=r"(r1), "=r"(r2), "=r"(r3) : "r"(a));
}
__device__ __forceinline__ void mma16816(float* c, const uint32_t* a,
                                         uint32_t b0, uint32_t b1) {
    asm volatile("mma.sync.aligned.m16n8k16.row.col.f32.f16.f16.f32 "
                 "{%0,%1,%2,%3}, {%4,%5,%6,%7}, {%8,%9}, {%0,%1,%2,%3};"
                 : "+f"(c[0]), "+f"(c[1]), "+f"(c[2]), "+f"(c[3])
                 : "r"(a[0]), "r"(a[1]), "r"(a[2]), "r"(a[3]), "r"(b0), "r"(b1));
}
// fp32x4 -> packed fp16x4
__device__ __forceinline__ unsigned long long cvt4h(float4 f) {
    __half2 p0 = __floats2half2_rn(f.x, f.y);
    __half2 p1 = __floats2half2_rn(f.z, f.w);
    union { __half2 h[2]; unsigned long long u; } r;
    r.h[0] = p0; r.h[1] = p1;
    return r.u;
}
__device__ __forceinline__ float tanh_fast(float x) {
    float t = __expf(2.f * x);
    return 1.f - __fdividef(2.f, t + 1.f);
}

// SMEM layout (bytes)
#define SO_AHI  0                              // 2 x AS1 fp16 = 36864
#define SO_BF   (SO_AHI + 2 * AS1 * 2)         // 36864: 2 x BF1 fp32 = 34816
#define SO_BSH  (SO_BF + 2 * BF1 * 4)          // 71680: KC*BPAD fp16 = 9216
#define SO_RED  (SO_BSH + KC * BPAD * 2)       // 80896: 4*64 fp32 = 1024
#define SO_SMX  (SO_RED + 4 * NT * 4)          // 81920: 256 fp32 = 1024
#define SMEM_SZ (SO_SMX + 256 * 4)             // 82944  (x2 CTA = 162KB)

// ---------------------------------------------------------------------------
// Kernel W-pack: W[:, :384] -> fp16
// ---------------------------------------------------------------------------
__global__ void __launch_bounds__(96) wpack_kernel(const float* __restrict__ W)
{
    int h = blockIdx.x, k = threadIdx.x * 4;
    float4 f = *(const float4*)&W[h * (4 * HH) + k];
    *(unsigned long long*)&g_whi[h * K3 + k] = cvt4h(f);
}

// ---------------------------------------------------------------------------
// Kernel A: d[b,h] = W[h,384:512] . dec[b,:]  (fp32, exact)
// ---------------------------------------------------------------------------
__global__ void __launch_bounds__(HH) dvec_kernel(const float* __restrict__ dec,
                                                  const float* __restrict__ W)
{
    __shared__ float4 sdec[HH / 4];
    int b = blockIdx.x, h = threadIdx.x;
    if (h < HH / 4) sdec[h] = *(const float4*)&dec[b * HH + h * 4];
    __syncthreads();
    const float4* w4 = (const float4*)(W + h * (4 * HH) + 3 * HH);
    float s0 = 0.f, s1 = 0.f, s2 = 0.f, s3 = 0.f;
#pragma unroll 8
    for (int i = 0; i < 32; i++) {
        float4 wv = w4[i];
        float4 dv = sdec[i];
        s0 += wv.x * dv.x; s1 += wv.y * dv.y;
        s2 += wv.z * dv.z; s3 += wv.w * dv.w;
    }
    g_dvec[b * HH + h] = (s0 + s1) + (s2 + s3);
}

// ---------------------------------------------------------------------------
// Kernel B: pipelined fp16 HMMA GEMM (KC=64) + tanh/v epilogue + fused softmax
// ---------------------------------------------------------------------------
__global__ void __launch_bounds__(256, 2)
score_kernel(const float* __restrict__ adj,
             const float* __restrict__ sta,
             const float* __restrict__ dyn,
             const float* __restrict__ v,
             float* __restrict__ out)
{
    extern __shared__ __align__(16) char smem[];
    __half* As_hi = (__half*)(smem + SO_AHI);
    float*  Bf    = (float*)(smem + SO_BF);
    __half* Bs_h  = (__half*)(smem + SO_BSH);
    float*  red   = (float*)(smem + SO_RED);
    float*  smx   = (float*)(smem + SO_SMX);

    const int tid  = threadIdx.x;
    const int lane = tid & 31;
    const int wrp  = tid >> 5;
    const int wm   = wrp >> 1;       // 0..3 (h quarter)
    const int wn   = wrp & 1;        // 0..1 (n half)
    const int b  = blockIdx.y;
    const int n0 = blockIdx.x * NT;

    const float* srcs[3] = {
        adj + (size_t)b * HH * NNODE,
        sta + (size_t)b * HH * NNODE,
        dyn + (size_t)b * HH * NNODE };

    const uint32_t uAhi = smem_u32(As_hi);
    const uint32_t uBf  = smem_u32(Bf);
    auto stage = [&](int it, int s) {
        const int k0 = it * KC;
        // A: g_whi[h][k0..k0+63], 128 rows x 8 chunks of 16B
#pragma unroll
        for (int i = 0; i < 4; i++) {
            int idx = tid + i * 256;
            int row = idx >> 3, q = idx & 7;
            uint32_t doff = (uint32_t)((s * AS1 + row * APAD + q * 8) * 2);
            CP16(uAhi + doff, &g_whi[row * K3 + k0 + q * 8]);
        }
        // B: hidden[b][k0+k][n0..n0+63] fp32, 64 k-rows x 16 chunks, zero-fill OOB
#pragma unroll
        for (int i = 0; i < 4; i++) {
            int idx = tid + i * 256;
            int krow = idx >> 4, q = idx & 15;
            int kg = k0 + krow;
            const float* src = srcs[kg >> 7] + (size_t)(kg & 127) * NNODE + n0 + q * 4;
            uint32_t doff = (uint32_t)((s * BF1 + krow * BFW + q * 4) * 4);
            uint32_t nb = (n0 + q * 4 < NNODE) ? 16u : 0u;
            CP16Z(uBf + doff, src, nb);
        }
        CP_COMMIT();
    };

    float acc[2][4][4];
#pragma unroll
    for (int mt = 0; mt < 2; mt++)
#pragma unroll
        for (int nt = 0; nt < 4; nt++)
#pragma unroll
            for (int c = 0; c < 4; c++) acc[mt][nt][c] = 0.f;

    const uint32_t bshU = smem_u32(Bs_h);
    const int aRow = wm * 32 + (lane & 15);        // + mt*16
    const int aCol = (lane >> 4) * 8;              // + ks*16
    const int bRow = (lane & 15);                  // + ks*16
    const int bCol = wn * 32 + (lane >> 4) * 8;    // + ntg*16

    stage(0, 0);                                    // prologue

    for (int it = 0; it < NCH; it++) {
        const int s = it & 1;
        __syncthreads();                            // prev compute reads done
        if (it + 1 < NCH) { stage(it + 1, s ^ 1); CP_WAIT(1); }
        else              { CP_WAIT(0); }
        __syncthreads();                            // stage s visible

        // ---- convert B fp32 -> fp16 (64 rows x 16 float4)
#pragma unroll
        for (int i = 0; i < 4; i++) {
            int idx = tid + i * 256;
            int krow = idx >> 4, q = idx & 15;
            float4 f = *(float4*)&Bf[s * BF1 + krow * BFW + q * 4];
            *(unsigned long long*)&Bs_h[krow * BPAD + q * 4] = cvt4h(f);
        }
        __syncthreads();                            // Bs ready

        const uint32_t aOffS = (uint32_t)(s * AS1 * 2);
#pragma unroll
        for (int ks = 0; ks < 4; ks++) {
            uint32_t ah[2][4];
#pragma unroll
            for (int mt = 0; mt < 2; mt++) {
                uint32_t off = aOffS + (uint32_t)(((aRow + mt * 16) * APAD + ks * 16 + aCol) * 2);
                ldsm_x4(ah[mt][0], ah[mt][1], ah[mt][2], ah[mt][3], uAhi + off);
            }
            uint32_t bh[8];
#pragma unroll
            for (int ntg = 0; ntg < 2; ntg++) {
                uint32_t off = (uint32_t)(((ks * 16 + bRow) * BPAD + bCol + ntg * 16) * 2);
                ldsm_x4_t(bh[ntg*4+0], bh[ntg*4+1], bh[ntg*4+2], bh[ntg*4+3], bshU + off);
            }
#pragma unroll
            for (int mt = 0; mt < 2; mt++)
#pragma unroll
                for (int nt = 0; nt < 4; nt++)
                    mma16816(acc[mt][nt], ah[mt], bh[nt*2+0], bh[nt*2+1]);
        }
    }

    // ---- epilogue: tanh(acc + d) * v, reduce over h -> logits
    const int g = lane >> 2, t = lane & 3;
    const float* dp = g_dvec + b * HH;
    float d0[2], d1[2], v0[2], v1[2];
#pragma unroll
    for (int mt = 0; mt < 2; mt++) {
        int h0 = wm * 32 + mt * 16 + g;
        d0[mt] = dp[h0];     d1[mt] = dp[h0 + 8];
        v0[mt] = v[h0];      v1[mt] = v[h0 + 8];
    }
    float p[4][2];
#pragma unroll
    for (int nt = 0; nt < 4; nt++)
#pragma unroll
        for (int c = 0; c < 2; c++) {
            float sacc = 0.f;
#pragma unroll
            for (int mt = 0; mt < 2; mt++)
                sacc += v0[mt] * tanh_fast(acc[mt][nt][c]     + d0[mt])
                      + v1[mt] * tanh_fast(acc[mt][nt][c + 2] + d1[mt]);
            p[nt][c] = sacc;
        }
#pragma unroll
    for (int m = 4; m <= 16; m <<= 1)
#pragma unroll
        for (int nt = 0; nt < 4; nt++)
#pragma unroll
            for (int c = 0; c < 2; c++)
                p[nt][c] += __shfl_xor_sync(0xFFFFFFFFu, p[nt][c], m);
    if (g == 0) {
#pragma unroll
        for (int nt = 0; nt < 4; nt++)
#pragma unroll
            for (int c = 0; c < 2; c++)
                red[wm * NT + wn * 32 + nt * 8 + t * 2 + c] = p[nt][c];
    }
    __syncthreads();
    if (tid < NT) {
        float sacc = red[0*NT+tid] + red[1*NT+tid] + red[2*NT+tid] + red[3*NT+tid];
        int n = n0 + tid;
        if (n < NNODE) g_attn[b * NPAD + n] = sacc;
    }

    // ---- fused softmax: last CTA of batch b does the row softmax
    __shared__ int is_last;
    __syncthreads();              // all logit writes issued
    __threadfence();              // order writes before the count
    if (tid == 0) is_last = (atomicAdd(&g_cnt[b], 1) == NTILES - 1);
    __syncthreads();
    if (is_last) {
        const float* row = &g_attn[b * NPAD];
        float m = -INFINITY;
        for (int n = tid; n < NNODE; n += 256) m = fmaxf(m, row[n]);
        smx[tid] = m;  __syncthreads();
        for (int sred = 128; sred > 0; sred >>= 1) {
            if (tid < sred) smx[tid] = fmaxf(smx[tid], smx[tid + sred]);
            __syncthreads();
        }
        m = smx[0];  __syncthreads();

        float sum = 0.f;
        for (int n = tid; n < NNODE; n += 256) sum += __expf(row[n] - m);
        smx[tid] = sum;  __syncthreads();
        for (int sred = 128; sred > 0; sred >>= 1) {
            if (tid < sred) smx[tid] += smx[tid + sred];
            __syncthreads();
        }
        float inv = 1.f / smx[0];

        for (int n = tid; n < NNODE; n += 256)
            out[b * NNODE + n] = __expf(row[n] - m) * inv;

        __syncthreads();
        if (tid == 0) g_cnt[b] = 0;   // reset for next graph replay
    }
}

// ---------------------------------------------------------------------------
extern "C" void kernel_launch(void* const* d_in, const int* in_sizes, int n_in,
                              void* d_out, int out_size)
{
    const float* adj = (const float*)d_in[0];
    const float* sta = (const float*)d_in[1];
    const float* dyn = (const float*)d_in[2];
    const float* dec = (const float*)d_in[3];
    const float* v   = (const float*)d_in[4];
    const float* W   = (const float*)d_in[5];
    float* out = (float*)d_out;

    cudaFuncSetAttribute(score_kernel,
                         cudaFuncAttributeMaxDynamicSharedMemorySize, SMEM_SZ);

    wpack_kernel<<<HH, 96>>>(W);
    dvec_kernel<<<BB, HH>>>(dec, W);
    dim3 grid(NTILES, BB);                       // (16, 256)
    score_kernel<<<grid, 256, SMEM_SZ>>>(adj, sta, dyn, v, out);
}

// round 13
// speedup vs baseline: 1.1325x; 1.0033x over previous
#include <cuda_runtime.h>
#include <cuda_fp16.h>
#include <cstdint>
#include <cstddef>
#include <math.h>

#define BB    256
#define HH    128
#define NNODE 1000
#define NPAD  1024
#define K3    384
#define KC    64          // k per chunk (4 x k16 steps)
#define NCH   (K3 / KC)   // 6
#define NT    64          // n per CTA
#define NTILES (NPAD / NT) // 16 CTAs per batch
#define APAD  72          // As row stride (fp16)
#define BPAD  72          // Bs row stride (fp16)
#define BFW   68          // Bf fp32 staging row stride (floats)

#define AS1   (HH * APAD)     // 9216 halfs per A buffer
#define BF1   (KC * BFW)      // 4352 floats per Bf buffer

// ---------------- scratch (__device__ globals) -----------------------------
__device__ float g_dvec[BB * HH];
__device__ float g_attn[BB * NPAD];
__device__ __half g_whi[HH * K3];
__device__ int   g_cnt[BB];              // zero-init; reset after use (graph-safe)

// ---------------- helpers --------------------------------------------------
__device__ __forceinline__ uint32_t smem_u32(const void* p) {
    uint32_t a;
    asm("{ .reg .u64 t; cvta.to.shared.u64 t, %1; cvt.u32.u64 %0, t; }" : "=r"(a) : "l"(p));
    return a;
}
#define CP16(dst, src) \
    asm volatile("cp.async.cg.shared.global [%0], [%1], 16;" :: "r"(dst), "l"(src))
#define CP16Z(dst, src, nb) \
    asm volatile("cp.async.cg.shared.global [%0], [%1], 16, %2;" :: "r"(dst), "l"(src), "r"(nb))
#define CP_COMMIT() asm volatile("cp.async.commit_group;")
#define CP_WAIT(n)  asm volatile("cp.async.wait_group %0;" :: "n"(n))

__device__ __forceinline__ void ldsm_x4(uint32_t& r0, uint32_t& r1,
                                        uint32_t& r2, uint32_t& r3, uint32_t a) {
    asm volatile("ldmatrix.sync.aligned.m8n8.x4.shared.b16 {%0,%1,%2,%3}, [%4];"
                 : "=r"(r0), "=r"(r1), "=r"(r2), "=r"(r3) : "r"(a));
}
__device__ __forceinline__ void ldsm_x4_t(uint32_t& r0, uint32_t& r1,
                                          uint32_t& r2, uint32_t& r3, uint32_t a) {
    asm volatile("ldmatrix.sync.aligned.m8n8.x4.trans.shared.b16 {%0,%1,%2,%3}, [%4];"
                 : "=r"(r0), "=r"(r1), "=r"(r2), "=r"(r3) : "r"(a));
}
__device__ __forceinline__ void mma16816(float* c, const uint32_t* a,
                                         uint32_t b0, uint32_t b1) {
    asm volatile("mma.sync.aligned.m16n8k16.row.col.f32.f16.f16.f32 "
                 "{%0,%1,%2,%3}, {%4,%5,%6,%7}, {%8,%9}, {%0,%1,%2,%3};"
                 : "+f"(c[0]), "+f"(c[1]), "+f"(c[2]), "+f"(c[3])
                 : "r"(a[0]), "r"(a[1]), "r"(a[2]), "r"(a[3]), "r"(b0), "r"(b1));
}
// fp32x4 -> packed fp16x4
__device__ __forceinline__ unsigned long long cvt4h(float4 f) {
    __half2 p0 = __floats2half2_rn(f.x, f.y);
    __half2 p1 = __floats2half2_rn(f.z, f.w);
    union { __half2 h[2]; unsigned long long u; } r;
    r.h[0] = p0; r.h[1] = p1;
    return r.u;
}
__device__ __forceinline__ float tanh_fast(float x) {
    float t = __expf(2.f * x);
    return 1.f - __fdividef(2.f, t + 1.f);
}

// SMEM layout (bytes)
#define SO_AHI  0                              // 2 x AS1 fp16 = 36864
#define SO_BF   (SO_AHI + 2 * AS1 * 2)         // 36864: 2 x BF1 fp32 = 34816
#define SO_BSH  (SO_BF + 2 * BF1 * 4)          // 71680: KC*BPAD fp16 = 9216
#define SO_RED  (SO_BSH + KC * BPAD * 2)       // 80896: 4*64 fp32 = 1024
#define SO_SMX  (SO_RED + 4 * NT * 4)          // 81920: 256 fp32 = 1024
#define SMEM_SZ (SO_SMX + 256 * 4)             // 82944  (x2 CTA = 162KB)

// ---------------------------------------------------------------------------
// Prep kernel (merged): CTAs [0,128) pack W row -> fp16; CTAs [128,384) dvec
// ---------------------------------------------------------------------------
__global__ void __launch_bounds__(HH) prep_kernel(const float* __restrict__ W,
                                                  const float* __restrict__ dec)
{
    const int bid = blockIdx.x;
    const int tid = threadIdx.x;
    if (bid < HH) {
        // ---- wpack: W[bid, 0:384] -> g_whi
        if (tid < K3 / 4) {
            int k = tid * 4;
            float4 f = *(const float4*)&W[bid * (4 * HH) + k];
            *(unsigned long long*)&g_whi[bid * K3 + k] = cvt4h(f);
        }
    } else {
        // ---- dvec: d[b,h] = W[h,384:512] . dec[b,:]
        __shared__ float4 sdec[HH / 4];
        int b = bid - HH, h = tid;
        if (h < HH / 4) sdec[h] = *(const float4*)&dec[b * HH + h * 4];
        __syncthreads();
        const float4* w4 = (const float4*)(W + h * (4 * HH) + 3 * HH);
        float s0 = 0.f, s1 = 0.f, s2 = 0.f, s3 = 0.f;
#pragma unroll 8
        for (int i = 0; i < 32; i++) {
            float4 wv = w4[i];
            float4 dv = sdec[i];
            s0 += wv.x * dv.x; s1 += wv.y * dv.y;
            s2 += wv.z * dv.z; s3 += wv.w * dv.w;
        }
        g_dvec[b * HH + h] = (s0 + s1) + (s2 + s3);
    }
}

// ---------------------------------------------------------------------------
// Kernel B: pipelined fp16 HMMA GEMM (KC=64) + tanh/v epilogue + fused softmax
//           A-ldsm hoisted above B-convert to hide smem latency
// ---------------------------------------------------------------------------
__global__ void __launch_bounds__(256, 2)
score_kernel(const float* __restrict__ adj,
             const float* __restrict__ sta,
             const float* __restrict__ dyn,
             const float* __restrict__ v,
             float* __restrict__ out)
{
    extern __shared__ __align__(16) char smem[];
    __half* As_hi = (__half*)(smem + SO_AHI);
    float*  Bf    = (float*)(smem + SO_BF);
    __half* Bs_h  = (__half*)(smem + SO_BSH);
    float*  red   = (float*)(smem + SO_RED);
    float*  smx   = (float*)(smem + SO_SMX);

    const int tid  = threadIdx.x;
    const int lane = tid & 31;
    const int wrp  = tid >> 5;
    const int wm   = wrp >> 1;       // 0..3 (h quarter)
    const int wn   = wrp & 1;        // 0..1 (n half)
    const int b  = blockIdx.y;
    const int n0 = blockIdx.x * NT;

    const float* srcs[3] = {
        adj + (size_t)b * HH * NNODE,
        sta + (size_t)b * HH * NNODE,
        dyn + (size_t)b * HH * NNODE };

    const uint32_t uAhi = smem_u32(As_hi);
    const uint32_t uBf  = smem_u32(Bf);
    auto stage = [&](int it, int s) {
        const int k0 = it * KC;
        // A: g_whi[h][k0..k0+63], 128 rows x 8 chunks of 16B
#pragma unroll
        for (int i = 0; i < 4; i++) {
            int idx = tid + i * 256;
            int row = idx >> 3, q = idx & 7;
            uint32_t doff = (uint32_t)((s * AS1 + row * APAD + q * 8) * 2);
            CP16(uAhi + doff, &g_whi[row * K3 + k0 + q * 8]);
        }
        // B: hidden[b][k0+k][n0..n0+63] fp32, 64 k-rows x 16 chunks, zero-fill OOB
#pragma unroll
        for (int i = 0; i < 4; i++) {
            int idx = tid + i * 256;
            int krow = idx >> 4, q = idx & 15;
            int kg = k0 + krow;
            const float* src = srcs[kg >> 7] + (size_t)(kg & 127) * NNODE + n0 + q * 4;
            uint32_t doff = (uint32_t)((s * BF1 + krow * BFW + q * 4) * 4);
            uint32_t nb = (n0 + q * 4 < NNODE) ? 16u : 0u;
            CP16Z(uBf + doff, src, nb);
        }
        CP_COMMIT();
    };

    float acc[2][4][4];
#pragma unroll
    for (int mt = 0; mt < 2; mt++)
#pragma unroll
        for (int nt = 0; nt < 4; nt++)
#pragma unroll
            for (int c = 0; c < 4; c++) acc[mt][nt][c] = 0.f;

    const uint32_t bshU = smem_u32(Bs_h);
    const int aRow = wm * 32 + (lane & 15);        // + mt*16
    const int aCol = (lane >> 4) * 8;              // + ks*16
    const int bRow = (lane & 15);                  // + ks*16
    const int bCol = wn * 32 + (lane >> 4) * 8;    // + ntg*16

    stage(0, 0);                                    // prologue

    for (int it = 0; it < NCH; it++) {
        const int s = it & 1;
        __syncthreads();                            // prev compute reads done
        if (it + 1 < NCH) { stage(it + 1, s ^ 1); CP_WAIT(1); }
        else              { CP_WAIT(0); }
        __syncthreads();                            // stage s visible

        // ---- hoisted A ldsm for all 4 k-steps (latency hidden under convert)
        const uint32_t aOffS = (uint32_t)(s * AS1 * 2);
        uint32_t ah[4][2][4];
#pragma unroll
        for (int ks = 0; ks < 4; ks++)
#pragma unroll
            for (int mt = 0; mt < 2; mt++) {
                uint32_t off = aOffS + (uint32_t)(((aRow + mt * 16) * APAD + ks * 16 + aCol) * 2);
                ldsm_x4(ah[ks][mt][0], ah[ks][mt][1], ah[ks][mt][2], ah[ks][mt][3], uAhi + off);
            }

        // ---- convert B fp32 -> fp16 (64 rows x 16 float4)
#pragma unroll
        for (int i = 0; i < 4; i++) {
            int idx = tid + i * 256;
            int krow = idx >> 4, q = idx & 15;
            float4 f = *(float4*)&Bf[s * BF1 + krow * BFW + q * 4];
            *(unsigned long long*)&Bs_h[krow * BPAD + q * 4] = cvt4h(f);
        }
        __syncthreads();                            // Bs ready

#pragma unroll
        for (int ks = 0; ks < 4; ks++) {
            uint32_t bh[8];
#pragma unroll
            for (int ntg = 0; ntg < 2; ntg++) {
                uint32_t off = (uint32_t)(((ks * 16 + bRow) * BPAD + bCol + ntg * 16) * 2);
                ldsm_x4_t(bh[ntg*4+0], bh[ntg*4+1], bh[ntg*4+2], bh[ntg*4+3], bshU + off);
            }
#pragma unroll
            for (int mt = 0; mt < 2; mt++)
#pragma unroll
                for (int nt = 0; nt < 4; nt++)
                    mma16816(acc[mt][nt], ah[ks][mt], bh[nt*2+0], bh[nt*2+1]);
        }
    }

    // ---- epilogue: tanh(acc + d) * v, reduce over h -> logits
    const int g = lane >> 2, t = lane & 3;
    const float* dp = g_dvec + b * HH;
    float d0[2], d1[2], v0[2], v1[2];
#pragma unroll
    for (int mt = 0; mt < 2; mt++) {
        int h0 = wm * 32 + mt * 16 + g;
        d0[mt] = dp[h0];     d1[mt] = dp[h0 + 8];
        v0[mt] = v[h0];      v1[mt] = v[h0 + 8];
    }
    float p[4][2];
#pragma unroll
    for (int nt = 0; nt < 4; nt++)
#pragma unroll
        for (int c = 0; c < 2; c++) {
            float sacc = 0.f;
#pragma unroll
            for (int mt = 0; mt < 2; mt++)
                sacc += v0[mt] * tanh_fast(acc[mt][nt][c]     + d0[mt])
                      + v1[mt] * tanh_fast(acc[mt][nt][c + 2] + d1[mt]);
            p[nt][c] = sacc;
        }
#pragma unroll
    for (int m = 4; m <= 16; m <<= 1)
#pragma unroll
        for (int nt = 0; nt < 4; nt++)
#pragma unroll
            for (int c = 0; c < 2; c++)
                p[nt][c] += __shfl_xor_sync(0xFFFFFFFFu, p[nt][c], m);
    if (g == 0) {
#pragma unroll
        for (int nt = 0; nt < 4; nt++)
#pragma unroll
            for (int c = 0; c < 2; c++)
                red[wm * NT + wn * 32 + nt * 8 + t * 2 + c] = p[nt][c];
    }
    __syncthreads();
    if (tid < NT) {
        float sacc = red[0*NT+tid] + red[1*NT+tid] + red[2*NT+tid] + red[3*NT+tid];
        int n = n0 + tid;
        if (n < NNODE) g_attn[b * NPAD + n] = sacc;
    }

    // ---- fused softmax: last CTA of batch b does the row softmax
    __shared__ int is_last;
    __syncthreads();              // all logit writes issued
    __threadfence();              // order writes before the count
    if (tid == 0) is_last = (atomicAdd(&g_cnt[b], 1) == NTILES - 1);
    __syncthreads();
    if (is_last) {
        const float* row = &g_attn[b * NPAD];
        float m = -INFINITY;
        for (int n = tid; n < NNODE; n += 256) m = fmaxf(m, row[n]);
        smx[tid] = m;  __syncthreads();
        for (int sred = 128; sred > 0; sred >>= 1) {
            if (tid < sred) smx[tid] = fmaxf(smx[tid], smx[tid + sred]);
            __syncthreads();
        }
        m = smx[0];  __syncthreads();

        float sum = 0.f;
        for (int n = tid; n < NNODE; n += 256) sum += __expf(row[n] - m);
        smx[tid] = sum;  __syncthreads();
        for (int sred = 128; sred > 0; sred >>= 1) {
            if (tid < sred) smx[tid] += smx[tid + sred];
            __syncthreads();
        }
        float inv = 1.f / smx[0];

        for (int n = tid; n < NNODE; n += 256)
            out[b * NNODE + n] = __expf(row[n] - m) * inv;

        __syncthreads();
        if (tid == 0) g_cnt[b] = 0;   // reset for next graph replay
    }
}

// ---------------------------------------------------------------------------
extern "C" void kernel_launch(void* const* d_in, const int* in_sizes, int n_in,
                              void* d_out, int out_size)
{
    const float* adj = (const float*)d_in[0];
    const float* sta = (const float*)d_in[1];
    const float* dyn = (const float*)d_in[2];
    const float* dec = (const float*)d_in[3];
    const float* v   = (const float*)d_in[4];
    const float* W   = (const float*)d_in[5];
    float* out = (float*)d_out;

    cudaFuncSetAttribute(score_kernel,
                         cudaFuncAttributeMaxDynamicSharedMemorySize, SMEM_SZ);

    prep_kernel<<<HH + BB, HH>>>(W, dec);        // 384 CTAs: wpack + dvec
    dim3 grid(NTILES, BB);                       // (16, 256)
    score_kernel<<<grid, 256, SMEM_SZ>>>(adj, sta, dyn, v, out);
}